// round 3
// baseline (speedup 1.0000x reference)
#include <cuda_runtime.h>
#include <cuda_bf16.h>

// Problem constants (shapes fixed by the dataset).
#define MAXN   50000
#define MAXE   800000
#define INC    128
#define OUTC   64
#define BN_EPS 1e-5f

// ---------------- scratch (device globals; no allocations allowed) ----------
__device__ float g_h[MAXN * OUTC];       // h = x @ W
__device__ float g_agg[MAXN * OUTC];     // tanh(agg + bias)
__device__ int   g_deg[MAXN];            // in-degree incl. self loop
__device__ float g_dinv[MAXN];           // deg^{-1/2}
__device__ int   g_rowptr[MAXN + 1];     // CSR row pointers (capacity = deg)
__device__ int   g_cursor[MAXN];         // scatter cursors
__device__ int2  g_sw[MAXE];             // per-edge (src, bitcast norm), bucketed by dst
__device__ float g_sum[OUTC];            // BN channel sums
__device__ float g_sqsum[OUTC];          // BN channel sum of squares
__device__ int   g_is64;                 // edge_index dtype flag (1 = int64)

// ---------------- f32x2 packed-math helpers ---------------------------------
__device__ __forceinline__ unsigned long long pk2(float a, float b) {
    unsigned long long r;
    asm("mov.b64 %0, {%1, %2};" : "=l"(r) : "f"(a), "f"(b));
    return r;
}
__device__ __forceinline__ void fma2(unsigned long long& d,
                                     unsigned long long a,
                                     unsigned long long b) {
    asm("fma.rn.f32x2 %0, %1, %2, %0;" : "+l"(d) : "l"(a), "l"(b));
}
__device__ __forceinline__ float2 up2(unsigned long long v) {
    float2 f;
    asm("mov.b64 {%0, %1}, %2;" : "=f"(f.x), "=f"(f.y) : "l"(v));
    return f;
}
__device__ __forceinline__ float fast_tanh(float x) {
    float e = __expf(2.f * x);            // MUFU ex2
    return 1.f - __fdividef(2.f, e + 1.f); // MUFU rcp
}

// ---------------- kernel 1: init + dtype detect -----------------------------
__global__ void k_init(const int* __restrict__ ei32, int E, int n) {
    int i = blockIdx.x * blockDim.x + threadIdx.x;
    if (i < n) g_deg[i] = 1;
    if (blockIdx.x == 0) {
        __shared__ int flag;
        if (threadIdx.x == 0) flag = 0;
        __syncthreads();
        int checks = min(256, E);
        if ((int)threadIdx.x < checks) {
            // int64 data => every odd 32-bit word is a zero high word
            // (indices < 50000). int32 => these words are random indices.
            if (ei32[2 * threadIdx.x + 1] != 0) atomicOr(&flag, 1);
        }
        __syncthreads();
        if (threadIdx.x == 0) g_is64 = (flag == 0) ? 1 : 0;
        if (threadIdx.x < OUTC) { g_sum[threadIdx.x] = 0.f; g_sqsum[threadIdx.x] = 0.f; }
    }
}

// ---------------- kernel 2: degree ------------------------------------------
__global__ void k_deg(const int* __restrict__ ei, int E) {
    int e = blockIdx.x * blockDim.x + threadIdx.x;
    if (e >= E) return;
    int dst = g_is64 ? ei[2 * (E + e)] : ei[E + e];
    atomicAdd(&g_deg[dst], 1);
}

// ---------------- kernel 3: prefix scan + dinv + cursors ---------------------
// Single block, 1024 threads, sequential chunks + Hillis-Steele block scan.
__global__ __launch_bounds__(1024) void k_scan(int n) {
    __shared__ int part[1024];
    const int tid   = threadIdx.x;
    const int chunk = (n + 1023) >> 10;
    const int beg   = tid * chunk;
    const int end   = min(beg + chunk, n);

    int s = 0;
    for (int i = beg; i < end; i++) s += g_deg[i];
    part[tid] = s;
    __syncthreads();
    #pragma unroll
    for (int off = 1; off < 1024; off <<= 1) {
        int add = (tid >= off) ? part[tid - off] : 0;
        __syncthreads();
        part[tid] += add;
        __syncthreads();
    }
    int run = part[tid] - s;   // exclusive base
    for (int i = beg; i < end; i++) {
        int d = g_deg[i];
        g_rowptr[i] = run;
        g_cursor[i] = run;
        g_dinv[i]   = rsqrtf((float)d);
        run += d;
    }
    if (tid == 1023) g_rowptr[n] = part[1023];
}

// ---------------- kernel 4: scatter edges into CSR buckets -------------------
__global__ __launch_bounds__(256) void k_scatter(const int* __restrict__ ei, int E) {
    int e = blockIdx.x * blockDim.x + threadIdx.x;
    if (e >= E) return;
    int s, d;
    if (g_is64) { s = ei[2 * e]; d = ei[2 * (E + e)]; }
    else        { s = ei[e];     d = ei[E + e]; }
    float nrm = g_dinv[s] * g_dinv[d];
    int pos = atomicAdd(&g_cursor[d], 1);
    g_sw[pos] = make_int2(s, __float_as_int(nrm));
}

// ---------------- kernel 5: GEMM h = x @ W (f32x2) ---------------------------
// 256 threads, block tile 128 rows x 64 cols, K chunked by 32.
// Thread tile: 4 rows x 8 cols (cols split as [4c..4c+3] and [32+4c..32+4c+3]
// so the two LDS.128 W reads per k are bank-conflict-free).
#define BK 32
#define XS_STRIDE 33
__global__ __launch_bounds__(256) void k_gemm(const float* __restrict__ x,
                                              const float* __restrict__ W,
                                              int n) {
    __shared__ float xs[128 * XS_STRIDE];   // 16896 B
    __shared__ float ws[BK * OUTC];         //  8192 B

    const int tid  = threadIdx.x;
    const int row0 = blockIdx.x * 128;
    const int colg = tid & 7;               // column group
    const int rowg = tid >> 3;              // 0..31, rows rowg*4..rowg*4+3

    unsigned long long acc[4][4];
    #pragma unroll
    for (int r = 0; r < 4; r++)
        #pragma unroll
        for (int c = 0; c < 4; c++) acc[r][c] = 0ull;

    const float4* x4  = reinterpret_cast<const float4*>(x);
    const float4* W4  = reinterpret_cast<const float4*>(W);
    float4*       ws4 = reinterpret_cast<float4*>(ws);
    const float4* wsr = reinterpret_cast<const float4*>(ws);

    for (int kc = 0; kc < INC / BK; kc++) {
        // x chunk: 128 rows x 32 k -> xs (stride 33, scalar STS, conflict-free)
        {
            const int lrow = tid >> 3;      // 0..31
            const int kf4  = tid & 7;
            #pragma unroll
            for (int p = 0; p < 4; p++) {
                int r  = lrow + p * 32;
                int gr = row0 + r;
                float4 v = make_float4(0.f, 0.f, 0.f, 0.f);
                if (gr < n) v = x4[(size_t)gr * (INC / 4) + kc * 8 + kf4];
                float* dstp = &xs[r * XS_STRIDE + kf4 * 4];
                dstp[0] = v.x; dstp[1] = v.y; dstp[2] = v.z; dstp[3] = v.w;
            }
        }
        // W chunk: 32 k x 64 cols = 512 float4, 2 per thread
        {
            #pragma unroll
            for (int i = 0; i < 2; i++)
                ws4[tid + i * 256] = W4[kc * (BK * OUTC / 4) + tid + i * 256];
        }
        __syncthreads();

        #pragma unroll 4
        for (int k = 0; k < BK; k++) {
            float4 wa = wsr[k * 16 + colg];       // cols 4c..4c+3
            float4 wb = wsr[k * 16 + 8 + colg];   // cols 32+4c..32+4c+3
            unsigned long long wp0 = pk2(wa.x, wa.y);
            unsigned long long wp1 = pk2(wa.z, wa.w);
            unsigned long long wp2 = pk2(wb.x, wb.y);
            unsigned long long wp3 = pk2(wb.z, wb.w);
            #pragma unroll
            for (int r = 0; r < 4; r++) {
                float xv = xs[(rowg * 4 + r) * XS_STRIDE + k];
                unsigned long long xp = pk2(xv, xv);
                fma2(acc[r][0], xp, wp0);
                fma2(acc[r][1], xp, wp1);
                fma2(acc[r][2], xp, wp2);
                fma2(acc[r][3], xp, wp3);
            }
        }
        __syncthreads();
    }

    #pragma unroll
    for (int r = 0; r < 4; r++) {
        int gr = row0 + rowg * 4 + r;
        if (gr < n) {
            float2 a0 = up2(acc[r][0]);
            float2 a1 = up2(acc[r][1]);
            float2 a2 = up2(acc[r][2]);
            float2 a3 = up2(acc[r][3]);
            float4* hp = reinterpret_cast<float4*>(g_h) + (size_t)gr * 16;
            hp[colg]     = make_float4(a0.x, a0.y, a1.x, a1.y);
            hp[colg + 8] = make_float4(a2.x, a2.y, a3.x, a3.y);
        }
    }
}

// ---------------- kernel 6: CSR aggregate + bias + tanh + BN stats -----------
// 16 lanes per dst node (one float4 = 4 channels per lane). No atomics on the
// feature data; one coalesced 16B store per (node, lane).
__global__ __launch_bounds__(256) void k_agg(const float* __restrict__ bias, int n) {
    const int tid  = threadIdx.x;
    const int grp  = tid >> 4;
    const int sub  = tid & 15;
    const int gstride = gridDim.x * 16;
    const float4* h4 = reinterpret_cast<const float4*>(g_h);
    float4* a4 = reinterpret_cast<float4*>(g_agg);
    const float4 bv = reinterpret_cast<const float4*>(bias)[sub];

    float4 s4 = make_float4(0.f, 0.f, 0.f, 0.f);
    float4 q4 = make_float4(0.f, 0.f, 0.f, 0.f);

    for (int d = blockIdx.x * 16 + grp; d < n; d += gstride) {
        const int beg = g_rowptr[d];
        const int end = g_rowptr[d + 1] - 1;   // last slot is the self-loop slack
        const float di = g_dinv[d];
        const float d2 = di * di;
        float4 acc = h4[(size_t)d * 16 + sub];
        acc.x *= d2; acc.y *= d2; acc.z *= d2; acc.w *= d2;   // self loop

        int j = beg;
        for (; j + 1 < end; j += 2) {          // unroll 2 for gather MLP
            int2 sw0 = g_sw[j];
            int2 sw1 = g_sw[j + 1];
            float4 v0 = __ldg(&h4[(size_t)sw0.x * 16 + sub]);
            float4 v1 = __ldg(&h4[(size_t)sw1.x * 16 + sub]);
            float n0 = __int_as_float(sw0.y);
            float n1 = __int_as_float(sw1.y);
            acc.x += v0.x * n0; acc.y += v0.y * n0; acc.z += v0.z * n0; acc.w += v0.w * n0;
            acc.x += v1.x * n1; acc.y += v1.y * n1; acc.z += v1.z * n1; acc.w += v1.w * n1;
        }
        if (j < end) {
            int2 sw = g_sw[j];
            float4 v = __ldg(&h4[(size_t)sw.x * 16 + sub]);
            float nm = __int_as_float(sw.y);
            acc.x += v.x * nm; acc.y += v.y * nm; acc.z += v.z * nm; acc.w += v.w * nm;
        }

        float4 a;
        a.x = fast_tanh(acc.x + bv.x);
        a.y = fast_tanh(acc.y + bv.y);
        a.z = fast_tanh(acc.z + bv.z);
        a.w = fast_tanh(acc.w + bv.w);
        a4[(size_t)d * 16 + sub] = a;
        s4.x += a.x; s4.y += a.y; s4.z += a.z; s4.w += a.w;
        q4.x += a.x * a.x; q4.y += a.y * a.y; q4.z += a.z * a.z; q4.w += a.w * a.w;
    }

    __shared__ float4 shs[256], shq[256];
    shs[tid] = s4; shq[tid] = q4;
    __syncthreads();
    if (tid < 16) {
        float4 S = shs[tid], Q = shq[tid];
        for (int g = 1; g < 16; g++) {
            float4 s = shs[g * 16 + tid], q = shq[g * 16 + tid];
            S.x += s.x; S.y += s.y; S.z += s.z; S.w += s.w;
            Q.x += q.x; Q.y += q.y; Q.z += q.z; Q.w += q.w;
        }
        atomicAdd(&g_sum[tid * 4 + 0], S.x);
        atomicAdd(&g_sum[tid * 4 + 1], S.y);
        atomicAdd(&g_sum[tid * 4 + 2], S.z);
        atomicAdd(&g_sum[tid * 4 + 3], S.w);
        atomicAdd(&g_sqsum[tid * 4 + 0], Q.x);
        atomicAdd(&g_sqsum[tid * 4 + 1], Q.y);
        atomicAdd(&g_sqsum[tid * 4 + 2], Q.z);
        atomicAdd(&g_sqsum[tid * 4 + 3], Q.w);
    }
}

// ---------------- kernel 7: BN normalize -------------------------------------
__global__ __launch_bounds__(256) void k_norm(const float* __restrict__ gamma,
                                              const float* __restrict__ beta,
                                              float* __restrict__ out, int n) {
    const int total  = n * OUTC;
    const int stride = gridDim.x * blockDim.x;     // multiple of 64
    const int c      = threadIdx.x & 63;
    const float inv_n = 1.f / (float)n;
    float mean  = g_sum[c]   * inv_n;
    float var   = g_sqsum[c] * inv_n - mean * mean;
    float scale = gamma[c] * rsqrtf(var + BN_EPS);
    float shift = beta[c] - mean * scale;
    for (int i = blockIdx.x * blockDim.x + threadIdx.x; i < total; i += stride) {
        out[i] = g_agg[i] * scale + shift;
    }
}

// ---------------- launch -----------------------------------------------------
extern "C" void kernel_launch(void* const* d_in, const int* in_sizes, int n_in,
                              void* d_out, int out_size) {
    const float* x     = (const float*)d_in[0];
    const int*   ei    = (const int*)d_in[1];    // int32 view; dtype detected on device
    const float* W     = (const float*)d_in[2];
    const float* bias  = (const float*)d_in[3];
    const float* gamma = (const float*)d_in[4];
    const float* beta  = (const float*)d_in[5];
    float* out = (float*)d_out;

    const int n = in_sizes[0] / INC;             // 50000
    const int E = in_sizes[1] / 2;               // 800000 (same count for int32/int64 views)

    const int nblk = (n + 255) / 256;
    k_init<<<nblk, 256>>>(ei, E, n);
    k_deg<<<(E + 255) / 256, 256>>>(ei, E);
    k_scan<<<1, 1024>>>(n);
    k_gemm<<<(n + 127) / 128, 256>>>(x, W, n);
    k_scatter<<<(E + 255) / 256, 256>>>(ei, E);
    k_agg<<<(n + 15) / 16, 256>>>(bias, n);
    k_norm<<<512, 256>>>(gamma, beta, out, n);
}

// round 4
// speedup vs baseline: 2.2907x; 2.2907x over previous
#include <cuda_runtime.h>
#include <cuda_bf16.h>

// Problem constants (shapes fixed by the dataset).
#define MAXN   50000
#define INC    128
#define OUTC   64
#define BN_EPS 1e-5f

// ---------------- scratch (device globals; no allocations allowed) ----------
__device__ float g_h[MAXN * OUTC];     // h = x @ W
__device__ float g_agg[MAXN * OUTC];   // aggregation accumulator, then tanh output (in place)
__device__ int   g_deg[MAXN];          // in-degree incl. self loop
__device__ float g_dinv[MAXN];         // deg^{-1/2}
__device__ float g_sum[OUTC];          // BN channel sums
__device__ float g_sqsum[OUTC];        // BN channel sum of squares
__device__ int   g_is64;               // edge_index dtype flag (1 = int64)

// ---------------- helpers ----------------------------------------------------
__device__ __forceinline__ unsigned long long pk2(float a, float b) {
    unsigned long long r;
    asm("mov.b64 %0, {%1, %2};" : "=l"(r) : "f"(a), "f"(b));
    return r;
}
__device__ __forceinline__ void fma2(unsigned long long& d,
                                     unsigned long long a,
                                     unsigned long long b) {
    asm("fma.rn.f32x2 %0, %1, %2, %0;" : "+l"(d) : "l"(a), "l"(b));
}
__device__ __forceinline__ float2 up2(unsigned long long v) {
    float2 f;
    asm("mov.b64 {%0, %1}, %2;" : "=f"(f.x), "=f"(f.y) : "l"(v));
    return f;
}
__device__ __forceinline__ float fast_tanh(float x) {
    float e = __expf(2.f * x);              // MUFU ex2
    return 1.f - __fdividef(2.f, e + 1.f);  // MUFU rcp
}
__device__ __forceinline__ unsigned smem_u32(const void* p) {
    unsigned a;
    asm("{ .reg .u64 t; cvta.to.shared.u64 t, %1; cvt.u32.u64 %0, t; }"
        : "=r"(a) : "l"(p));
    return a;
}
__device__ __forceinline__ void cpa16(unsigned dst, const void* src, int srcsize) {
    asm volatile("cp.async.cg.shared.global [%0], [%1], 16, %2;"
                 :: "r"(dst), "l"(src), "r"(srcsize));
}
#define CPA_COMMIT() asm volatile("cp.async.commit_group;")
template <int N> __device__ __forceinline__ void cpa_wait() {
    asm volatile("cp.async.wait_group %0;" :: "n"(N));
}

// ---------------- kernel 1: init + dtype detect -----------------------------
__global__ void k_init(const int* __restrict__ ei32, int E, int n) {
    int i = blockIdx.x * blockDim.x + threadIdx.x;
    if (i < n) g_deg[i] = 1;
    if (blockIdx.x == 0) {
        __shared__ int flag;
        if (threadIdx.x == 0) flag = 0;
        __syncthreads();
        int checks = min(256, E);
        if ((int)threadIdx.x < checks) {
            // int64 data => every odd 32-bit word is a zero high word
            // (indices < 50000). int32 => these words are random indices.
            if (ei32[2 * threadIdx.x + 1] != 0) atomicOr(&flag, 1);
        }
        __syncthreads();
        if (threadIdx.x == 0) g_is64 = (flag == 0) ? 1 : 0;
        if (threadIdx.x < OUTC) { g_sum[threadIdx.x] = 0.f; g_sqsum[threadIdx.x] = 0.f; }
    }
}

// ---------------- kernel 2: degree ------------------------------------------
__global__ void k_deg(const int* __restrict__ ei, int E) {
    int e = blockIdx.x * blockDim.x + threadIdx.x;
    if (e >= E) return;
    int dst = g_is64 ? ei[2 * (E + e)] : ei[E + e];
    atomicAdd(&g_deg[dst], 1);
}

// ---------------- kernel 3: dinv --------------------------------------------
__global__ void k_dinv(int n) {
    int i = blockIdx.x * blockDim.x + threadIdx.x;
    if (i < n) g_dinv[i] = rsqrtf((float)g_deg[i]);   // deg >= 1 always
}

// ---------------- kernel 4: GEMM h = x @ W (f32x2, cp.async double buffer) --
// 256 threads, block tile 128 rows x 64 cols, K chunked by 32.
// Whole W (32 KB) resident in smem; x chunks double-buffered via cp.async.
// xs stride 36 floats (144 B, 16B-aligned rows): mainloop broadcast reads hit
// banks (4*row + k) % 32 — 4 distinct rows per warp -> conflict-free.
#define BK 32
#define XS_STRIDE 36
#define XS_CHUNK (128 * XS_STRIDE)          // floats per buffer
__global__ __launch_bounds__(256) void k_gemm(const float* __restrict__ x,
                                              const float* __restrict__ W,
                                              int n) {
    extern __shared__ float smem[];
    float* ws = smem;                       // 8192 floats (full W)
    float* xs = smem + INC * OUTC;          // 2 x 4608 floats

    const int tid  = threadIdx.x;
    const int row0 = blockIdx.x * 128;
    const int colg = tid & 7;               // 8 cols: [4c..4c+3] and [32+4c..32+4c+3]
    const int rowg = tid >> 3;              // 0..31, rows rowg*4..rowg*4+3
    const int lrow = tid >> 3;              // loader row base
    const int kf4  = tid & 7;               // loader float4 index in chunk

    const float4* x4 = reinterpret_cast<const float4*>(x);
    const float4* W4 = reinterpret_cast<const float4*>(W);
    const unsigned ws_a = smem_u32(ws);
    const unsigned xs_a = smem_u32(xs);

    // ---- prologue: async-load full W + x chunk 0 (group 0)
    #pragma unroll
    for (int i = 0; i < 8; i++)
        cpa16(ws_a + (tid + i * 256) * 16, W4 + tid + i * 256, 16);
    #pragma unroll
    for (int p = 0; p < 4; p++) {
        int r  = lrow + p * 32;
        int gr = row0 + r;
        cpa16(xs_a + (r * XS_STRIDE + kf4 * 4) * 4,
              x4 + (size_t)gr * (INC / 4) + kf4, gr < n ? 16 : 0);
    }
    CPA_COMMIT();

    unsigned long long acc[4][4];
    #pragma unroll
    for (int r = 0; r < 4; r++)
        #pragma unroll
        for (int c = 0; c < 4; c++) acc[r][c] = 0ull;

    const float4* wsr = reinterpret_cast<const float4*>(ws);

    #pragma unroll
    for (int kc = 0; kc < INC / BK; kc++) {
        if (kc < INC / BK - 1) {
            // async-load next x chunk into the other buffer
            const unsigned buf_a = xs_a + (((kc + 1) & 1) * XS_CHUNK) * 4;
            #pragma unroll
            for (int p = 0; p < 4; p++) {
                int r  = lrow + p * 32;
                int gr = row0 + r;
                cpa16(buf_a + (r * XS_STRIDE + kf4 * 4) * 4,
                      x4 + (size_t)gr * (INC / 4) + (kc + 1) * 8 + kf4,
                      gr < n ? 16 : 0);
            }
            CPA_COMMIT();
            cpa_wait<1>();
        } else {
            cpa_wait<0>();
        }
        __syncthreads();

        const float* xb = xs + (kc & 1) * XS_CHUNK;
        #pragma unroll 4
        for (int k = 0; k < BK; k++) {
            float4 wa = wsr[(kc * BK + k) * 16 + colg];
            float4 wb = wsr[(kc * BK + k) * 16 + 8 + colg];
            unsigned long long wp0 = pk2(wa.x, wa.y);
            unsigned long long wp1 = pk2(wa.z, wa.w);
            unsigned long long wp2 = pk2(wb.x, wb.y);
            unsigned long long wp3 = pk2(wb.z, wb.w);
            #pragma unroll
            for (int r = 0; r < 4; r++) {
                float xv = xb[(rowg * 4 + r) * XS_STRIDE + k];
                unsigned long long xp = pk2(xv, xv);
                fma2(acc[r][0], xp, wp0);
                fma2(acc[r][1], xp, wp1);
                fma2(acc[r][2], xp, wp2);
                fma2(acc[r][3], xp, wp3);
            }
        }
        __syncthreads();
    }

    // ---- epilogue: write h and agg = h * dinv^2 (self-loop term)
    #pragma unroll
    for (int r = 0; r < 4; r++) {
        int gr = row0 + rowg * 4 + r;
        if (gr < n) {
            float di = g_dinv[gr];
            float d2 = di * di;
            float2 a0 = up2(acc[r][0]);
            float2 a1 = up2(acc[r][1]);
            float2 a2 = up2(acc[r][2]);
            float2 a3 = up2(acc[r][3]);
            float4 h0 = make_float4(a0.x, a0.y, a1.x, a1.y);
            float4 h1 = make_float4(a2.x, a2.y, a3.x, a3.y);
            float4* hp = reinterpret_cast<float4*>(g_h)   + (size_t)gr * 16;
            float4* ap = reinterpret_cast<float4*>(g_agg) + (size_t)gr * 16;
            hp[colg]     = h0;
            hp[colg + 8] = h1;
            ap[colg]     = make_float4(h0.x * d2, h0.y * d2, h0.z * d2, h0.w * d2);
            ap[colg + 8] = make_float4(h1.x * d2, h1.y * d2, h1.z * d2, h1.w * d2);
        }
    }
}
#define GEMM_SMEM ((INC * OUTC + 2 * XS_CHUNK) * 4)

// ---------------- kernel 5: edge scatter (REDG.128) --------------------------
// 16 threads per edge; each thread handles one float4 (4 channels) and issues
// a single vector reduction (red.global.add.v4.f32).
__global__ __launch_bounds__(256) void k_edges(const int* __restrict__ ei, int E) {
    int t = blockIdx.x * blockDim.x + threadIdx.x;
    int e = t >> 4;
    if (e >= E) return;
    unsigned mask = __activemask();     // whole 16-groups exit together
    int lane = threadIdx.x & 31;
    int sub  = lane & 15;

    int s = 0, d = 0;
    float nrm = 0.f;
    if (sub == 0) {
        if (g_is64) { s = ei[2 * e]; d = ei[2 * (E + e)]; }
        else        { s = ei[e];     d = ei[E + e]; }
        nrm = g_dinv[s] * g_dinv[d];
    }
    int srcl = lane & 16;               // group leader lane (0 or 16)
    s   = __shfl_sync(mask, s, srcl);
    d   = __shfl_sync(mask, d, srcl);
    nrm = __shfl_sync(mask, nrm, srcl);

    float4 v = __ldg(reinterpret_cast<const float4*>(g_h) + (size_t)s * 16 + sub);
    float4* dst = reinterpret_cast<float4*>(g_agg) + (size_t)d * 16 + sub;
    asm volatile("red.global.add.v4.f32 [%0], {%1, %2, %3, %4};"
                 :: "l"(dst), "f"(v.x * nrm), "f"(v.y * nrm),
                    "f"(v.z * nrm), "f"(v.w * nrm)
                 : "memory");
}

// ---------------- kernel 6: bias + fast tanh (in place) + BN partial stats ---
__global__ __launch_bounds__(256) void k_tanh_stats(const float* __restrict__ bias, int n) {
    const int total  = n * OUTC;
    const int stride = gridDim.x * blockDim.x;     // multiple of 64
    const int c      = threadIdx.x & 63;           // channel fixed per thread
    const float b    = bias[c];
    float s = 0.f, s2 = 0.f;
    for (int i = blockIdx.x * blockDim.x + threadIdx.x; i < total; i += stride) {
        float a = fast_tanh(g_agg[i] + b);
        g_agg[i] = a;
        s  += a;
        s2 += a * a;
    }
    __shared__ float sh[256], sh2[256];
    sh[threadIdx.x]  = s;
    sh2[threadIdx.x] = s2;
    __syncthreads();
    if (threadIdx.x < 64) {
        float t  = sh[threadIdx.x]  + sh[threadIdx.x + 64]  + sh[threadIdx.x + 128]  + sh[threadIdx.x + 192];
        float t2 = sh2[threadIdx.x] + sh2[threadIdx.x + 64] + sh2[threadIdx.x + 128] + sh2[threadIdx.x + 192];
        atomicAdd(&g_sum[c],   t);
        atomicAdd(&g_sqsum[c], t2);
    }
}

// ---------------- kernel 7: BN normalize -------------------------------------
__global__ __launch_bounds__(256) void k_norm(const float* __restrict__ gamma,
                                              const float* __restrict__ beta,
                                              float* __restrict__ out, int n) {
    const int total  = n * OUTC;
    const int stride = gridDim.x * blockDim.x;     // multiple of 64
    const int c      = threadIdx.x & 63;
    const float inv_n = 1.f / (float)n;
    float mean  = g_sum[c]   * inv_n;
    float var   = g_sqsum[c] * inv_n - mean * mean;
    float scale = gamma[c] * rsqrtf(var + BN_EPS);
    float shift = beta[c] - mean * scale;
    for (int i = blockIdx.x * blockDim.x + threadIdx.x; i < total; i += stride) {
        out[i] = g_agg[i] * scale + shift;
    }
}

// ---------------- launch -----------------------------------------------------
extern "C" void kernel_launch(void* const* d_in, const int* in_sizes, int n_in,
                              void* d_out, int out_size) {
    const float* x     = (const float*)d_in[0];
    const int*   ei    = (const int*)d_in[1];    // int32 view; dtype detected on device
    const float* W     = (const float*)d_in[2];
    const float* bias  = (const float*)d_in[3];
    const float* gamma = (const float*)d_in[4];
    const float* beta  = (const float*)d_in[5];
    float* out = (float*)d_out;

    const int n = in_sizes[0] / INC;             // 50000
    const int E = in_sizes[1] / 2;               // 800000 (same count for int32/int64 views)

    cudaFuncSetAttribute(k_gemm, cudaFuncAttributeMaxDynamicSharedMemorySize, GEMM_SMEM);

    const int nblk = (n + 255) / 256;
    k_init<<<nblk, 256>>>(ei, E, n);
    k_deg<<<(E + 255) / 256, 256>>>(ei, E);
    k_dinv<<<nblk, 256>>>(n);
    k_gemm<<<(n + 127) / 128, 256, GEMM_SMEM>>>(x, W, n);
    {
        long long tthreads = (long long)E * 16;
        int gblk = (int)((tthreads + 255) / 256);
        k_edges<<<gblk, 256>>>(ei, E);
    }
    k_tanh_stats<<<1184, 256>>>(bias, n);
    k_norm<<<1184, 256>>>(gamma, beta, out, n);
}

// round 6
// speedup vs baseline: 2.5689x; 1.1214x over previous
#include <cuda_runtime.h>
#include <cuda_bf16.h>
#include <cstdint>

// Problem constants (shapes fixed by the dataset).
#define MAXN   50000
#define INC    128
#define OUTC   64
#define BN_EPS 1e-5f

// ---------------- scratch (device globals; no allocations allowed) ----------
__device__ float g_h[MAXN * OUTC];     // h = x @ W
__device__ float g_agg[MAXN * OUTC];   // aggregation accumulator, then tanh output (in place)
__device__ int   g_deg[MAXN];          // in-degree incl. self loop
__device__ float g_dinv[MAXN];         // deg^{-1/2}
__device__ float g_sum[OUTC];          // BN channel sums
__device__ float g_sqsum[OUTC];        // BN channel sum of squares
__device__ int   g_is64;               // edge_index dtype flag (1 = int64)

// ---------------- helpers ----------------------------------------------------
__device__ __forceinline__ float fast_tanh(float x) {
    float e = __expf(2.f * x);              // MUFU ex2
    return 1.f - __fdividef(2.f, e + 1.f);  // MUFU rcp
}
__device__ __forceinline__ uint32_t bfbits(float v) {
    return (uint32_t)__bfloat16_as_ushort(__float2bfloat16(v));
}
__device__ __forceinline__ float bfval(uint32_t b) {
    return __bfloat162float(__ushort_as_bfloat16((unsigned short)b));
}
// pack two floats' bf16 hi parts (lo 16 bits = first element)
__device__ __forceinline__ uint32_t pkhi(float a, float b) {
    return bfbits(a) | (bfbits(b) << 16);
}
__device__ __forceinline__ uint32_t pklo(float a, float b) {
    float ra = a - bfval(bfbits(a));
    float rb = b - bfval(bfbits(b));
    return bfbits(ra) | (bfbits(rb) << 16);
}
__device__ __forceinline__ void mma16816(float& d0, float& d1, float& d2, float& d3,
                                         uint32_t a0, uint32_t a1, uint32_t a2, uint32_t a3,
                                         uint32_t b0, uint32_t b1) {
    asm volatile("mma.sync.aligned.m16n8k16.row.col.f32.bf16.bf16.f32 "
                 "{%0,%1,%2,%3}, {%4,%5,%6,%7}, {%8,%9}, {%0,%1,%2,%3};"
                 : "+f"(d0), "+f"(d1), "+f"(d2), "+f"(d3)
                 : "r"(a0), "r"(a1), "r"(a2), "r"(a3), "r"(b0), "r"(b1));
}

// ---------------- kernel 1: init + dtype detect -----------------------------
__global__ void k_init(const int* __restrict__ ei32, int E, int n) {
    int i = blockIdx.x * blockDim.x + threadIdx.x;
    if (i < n) g_deg[i] = 1;
    if (blockIdx.x == 0) {
        __shared__ int flag;
        if (threadIdx.x == 0) flag = 0;
        __syncthreads();
        int checks = min(256, E);
        if ((int)threadIdx.x < checks) {
            // int64 data => every odd 32-bit word is a zero high word
            // (indices < 50000). int32 => these words are random indices.
            if (ei32[2 * threadIdx.x + 1] != 0) atomicOr(&flag, 1);
        }
        __syncthreads();
        if (threadIdx.x == 0) g_is64 = (flag == 0) ? 1 : 0;
        if (threadIdx.x < OUTC) { g_sum[threadIdx.x] = 0.f; g_sqsum[threadIdx.x] = 0.f; }
    }
}

// ---------------- kernel 2: degree ------------------------------------------
__global__ void k_deg(const int* __restrict__ ei, int E) {
    int e = blockIdx.x * blockDim.x + threadIdx.x;
    if (e >= E) return;
    int dst = g_is64 ? ei[2 * (E + e)] : ei[E + e];
    atomicAdd(&g_deg[dst], 1);
}

// ---------------- kernel 3: dinv --------------------------------------------
__global__ void k_dinv(int n) {
    int i = blockIdx.x * blockDim.x + threadIdx.x;
    if (i < n) g_dinv[i] = rsqrtf((float)g_deg[i]);   // deg >= 1 always
}

// ---------------- kernel 4: GEMM h = x @ W via HMMA bf16 hi/lo split ---------
// h = xh@Wh + xh@Wl + xl@Wh, all into one fp32 accumulator set.
// 256 threads = 8 warps; warp w owns rows row0 + w*16 .. +15; full N=64.
// A: loaded straight from global x in m16n8k16 fragment layout, converted to
//    bf16 hi/lo in registers (no smem).
// B: W pre-packed into per-lane fragment arrays in smem (uint2 per lane per
//    (kchunk, ntile)); mainloop B reads are LDS.64, conflict-free.
__global__ __launch_bounds__(256) void k_gemm(const float* __restrict__ x,
                                              const float* __restrict__ W,
                                              int n) {
    __shared__ uint2 bhi[8 * 8 * 32];   // [kc][nt][lane]  16 KB
    __shared__ uint2 blo[8 * 8 * 32];   //                 16 KB

    const int tid  = threadIdx.x;
    const int wid  = tid >> 5;
    const int lane = tid & 31;
    const int row0 = blockIdx.x * 128;

    // ---- pack W fragments (2048 uint2 per array; 8 entries per thread)
    #pragma unroll
    for (int i = 0; i < 8; i++) {
        int e    = tid + i * 256;
        int kc   = e >> 8;              // 0..7
        int nt   = (e >> 5) & 7;        // 0..7
        int l    = e & 31;
        int nn   = nt * 8 + (l >> 2);
        int k0   = kc * 16 + (l & 3) * 2;
        float w00 = W[(size_t)k0 * OUTC + nn];
        float w01 = W[(size_t)(k0 + 1) * OUTC + nn];
        float w10 = W[(size_t)(k0 + 8) * OUTC + nn];
        float w11 = W[(size_t)(k0 + 9) * OUTC + nn];
        bhi[e] = make_uint2(pkhi(w00, w01), pkhi(w10, w11));
        blo[e] = make_uint2(pklo(w00, w01), pklo(w10, w11));
    }
    __syncthreads();

    float acc[8][4];
    #pragma unroll
    for (int t = 0; t < 8; t++)
        #pragma unroll
        for (int j = 0; j < 4; j++) acc[t][j] = 0.f;

    const int r0 = row0 + wid * 16 + (lane >> 2);   // fragment rows r0, r0+8
    const int r1 = r0 + 8;
    const bool v0 = r0 < n, v1 = r1 < n;
    const float* xr0 = x + (size_t)r0 * INC + (lane & 3) * 2;
    const float* xr1 = x + (size_t)r1 * INC + (lane & 3) * 2;

    #pragma unroll
    for (int kc = 0; kc < 8; kc++) {
        // A fragment: 8 floats/lane in mma layout, converted to hi/lo bf16x2
        float2 e0 = v0 ? *reinterpret_cast<const float2*>(xr0 + kc * 16)
                       : make_float2(0.f, 0.f);
        float2 e1 = v1 ? *reinterpret_cast<const float2*>(xr1 + kc * 16)
                       : make_float2(0.f, 0.f);
        float2 e2 = v0 ? *reinterpret_cast<const float2*>(xr0 + kc * 16 + 8)
                       : make_float2(0.f, 0.f);
        float2 e3 = v1 ? *reinterpret_cast<const float2*>(xr1 + kc * 16 + 8)
                       : make_float2(0.f, 0.f);
        uint32_t ah0 = pkhi(e0.x, e0.y), al0 = pklo(e0.x, e0.y);
        uint32_t ah1 = pkhi(e1.x, e1.y), al1 = pklo(e1.x, e1.y);
        uint32_t ah2 = pkhi(e2.x, e2.y), al2 = pklo(e2.x, e2.y);
        uint32_t ah3 = pkhi(e3.x, e3.y), al3 = pklo(e3.x, e3.y);

        const uint2* bh = &bhi[(kc * 8) * 32 + lane];
        const uint2* bl = &blo[(kc * 8) * 32 + lane];
        #pragma unroll
        for (int nt = 0; nt < 8; nt++) {
            uint2 bH = bh[nt * 32];
            uint2 bL = bl[nt * 32];
            mma16816(acc[nt][0], acc[nt][1], acc[nt][2], acc[nt][3],
                     ah0, ah1, ah2, ah3, bH.x, bH.y);   // xh @ Wh
            mma16816(acc[nt][0], acc[nt][1], acc[nt][2], acc[nt][3],
                     ah0, ah1, ah2, ah3, bL.x, bL.y);   // xh @ Wl
            mma16816(acc[nt][0], acc[nt][1], acc[nt][2], acc[nt][3],
                     al0, al1, al2, al3, bH.x, bH.y);   // xl @ Wh
        }
    }

    // ---- epilogue: write h and agg = h * dinv^2 (self-loop term)
    const int c0 = (lane & 3) * 2;
    float d2a = 0.f, d2b = 0.f;
    if (v0) { float di = g_dinv[r0]; d2a = di * di; }
    if (v1) { float di = g_dinv[r1]; d2b = di * di; }
    #pragma unroll
    for (int nt = 0; nt < 8; nt++) {
        int c = nt * 8 + c0;
        if (v0) {
            float2 hv = make_float2(acc[nt][0], acc[nt][1]);
            *reinterpret_cast<float2*>(g_h   + (size_t)r0 * OUTC + c) = hv;
            *reinterpret_cast<float2*>(g_agg + (size_t)r0 * OUTC + c) =
                make_float2(hv.x * d2a, hv.y * d2a);
        }
        if (v1) {
            float2 hv = make_float2(acc[nt][2], acc[nt][3]);
            *reinterpret_cast<float2*>(g_h   + (size_t)r1 * OUTC + c) = hv;
            *reinterpret_cast<float2*>(g_agg + (size_t)r1 * OUTC + c) =
                make_float2(hv.x * d2b, hv.y * d2b);
        }
    }
}

// ---------------- kernel 5: edge scatter (REDG.128) --------------------------
// 16 threads per edge; each thread handles one float4 (4 channels) and issues
// a single vector reduction (red.global.add.v4.f32).
__global__ __launch_bounds__(256) void k_edges(const int* __restrict__ ei, int E) {
    int t = blockIdx.x * blockDim.x + threadIdx.x;
    int e = t >> 4;
    if (e >= E) return;
    unsigned mask = __activemask();     // whole 16-groups exit together
    int lane = threadIdx.x & 31;
    int sub  = lane & 15;

    int s = 0, d = 0;
    float nrm = 0.f;
    if (sub == 0) {
        if (g_is64) { s = ei[2 * e]; d = ei[2 * (E + e)]; }
        else        { s = ei[e];     d = ei[E + e]; }
        nrm = g_dinv[s] * g_dinv[d];
    }
    int srcl = lane & 16;               // group leader lane (0 or 16)
    s   = __shfl_sync(mask, s, srcl);
    d   = __shfl_sync(mask, d, srcl);
    nrm = __shfl_sync(mask, nrm, srcl);

    float4 v = __ldg(reinterpret_cast<const float4*>(g_h) + (size_t)s * 16 + sub);
    float4* dst = reinterpret_cast<float4*>(g_agg) + (size_t)d * 16 + sub;
    asm volatile("red.global.add.v4.f32 [%0], {%1, %2, %3, %4};"
                 :: "l"(dst), "f"(v.x * nrm), "f"(v.y * nrm),
                    "f"(v.z * nrm), "f"(v.w * nrm)
                 : "memory");
}

// ---------------- kernel 6: bias + fast tanh (in place) + BN partial stats ---
__global__ __launch_bounds__(256) void k_tanh_stats(const float* __restrict__ bias, int n) {
    const int total  = n * OUTC;
    const int stride = gridDim.x * blockDim.x;     // multiple of 64
    const int c      = threadIdx.x & 63;           // channel fixed per thread
    const float b    = bias[c];
    float s = 0.f, s2 = 0.f;
    for (int i = blockIdx.x * blockDim.x + threadIdx.x; i < total; i += stride) {
        float a = fast_tanh(g_agg[i] + b);
        g_agg[i] = a;
        s  += a;
        s2 += a * a;
    }
    __shared__ float sh[256], sh2[256];
    sh[threadIdx.x]  = s;
    sh2[threadIdx.x] = s2;
    __syncthreads();
    if (threadIdx.x < 64) {
        float t  = sh[threadIdx.x]  + sh[threadIdx.x + 64]  + sh[threadIdx.x + 128]  + sh[threadIdx.x + 192];
        float t2 = sh2[threadIdx.x] + sh2[threadIdx.x + 64] + sh2[threadIdx.x + 128] + sh2[threadIdx.x + 192];
        atomicAdd(&g_sum[c],   t);
        atomicAdd(&g_sqsum[c], t2);
    }
}

// ---------------- kernel 7: BN normalize -------------------------------------
__global__ __launch_bounds__(256) void k_norm(const float* __restrict__ gamma,
                                              const float* __restrict__ beta,
                                              float* __restrict__ out, int n) {
    const int total  = n * OUTC;
    const int stride = gridDim.x * blockDim.x;     // multiple of 64
    const int c      = threadIdx.x & 63;
    const float inv_n = 1.f / (float)n;
    float mean  = g_sum[c]   * inv_n;
    float var   = g_sqsum[c] * inv_n - mean * mean;
    float scale = gamma[c] * rsqrtf(var + BN_EPS);
    float shift = beta[c] - mean * scale;
    for (int i = blockIdx.x * blockDim.x + threadIdx.x; i < total; i += stride) {
        out[i] = g_agg[i] * scale + shift;
    }
}

// ---------------- launch -----------------------------------------------------
extern "C" void kernel_launch(void* const* d_in, const int* in_sizes, int n_in,
                              void* d_out, int out_size) {
    const float* x     = (const float*)d_in[0];
    const int*   ei    = (const int*)d_in[1];    // int32 view; dtype detected on device
    const float* W     = (const float*)d_in[2];
    const float* bias  = (const float*)d_in[3];
    const float* gamma = (const float*)d_in[4];
    const float* beta  = (const float*)d_in[5];
    float* out = (float*)d_out;

    const int n = in_sizes[0] / INC;             // 50000
    const int E = in_sizes[1] / 2;               // 800000 (same count for int32/int64 views)

    const int nblk = (n + 255) / 256;
    k_init<<<nblk, 256>>>(ei, E, n);
    k_deg<<<(E + 255) / 256, 256>>>(ei, E);
    k_dinv<<<nblk, 256>>>(n);
    k_gemm<<<(n + 127) / 128, 256>>>(x, W, n);
    {
        long long tthreads = (long long)E * 16;
        int gblk = (int)((tthreads + 255) / 256);
        k_edges<<<gblk, 256>>>(ei, E);
    }
    k_tanh_stats<<<1184, 256>>>(bias, n);
    k_norm<<<1184, 256>>>(gamma, beta, out, n);
}